// round 7
// baseline (speedup 1.0000x reference)
#include <cuda_runtime.h>
#include <cuda_fp16.h>
#include <cstdint>

// Problem constants
#define Bc   16
#define G    8
#define CPER 32
#define CIN  256
#define Jc   64
#define Hc   56
#define Wc   56
#define HW   (Hc * Wc)          // 3136

// Tiling
#define TILE_OR 4
#define NCOLS   58
#define NREAL   ((TILE_OR + 2) * NCOLS)   // 348
#define NPADR   384
#define NSPAT   (TILE_OR * NCOLS)         // 232
#define NTHREADS 256

// smem rows: 80 B (64 B data + 16 B pad) -> conflict-free ldmatrix, cheap addressing
#define RSTR    80
#define SM_A    0
#define SM_B    (NPADR * RSTR)            // 30720
#define BT_STR  (Jc * RSTR)               // 5120 per tap
#define SMEM_USED (SM_B + 9 * BT_STR)     // 76800
#define SMEM_BYTES (SMEM_USED + 1024)

#define OSTR 260                          // epilogue scratch stride (floats)

// Prepped operands
__device__ __half wgt_f16[G * 9 * Jc * CPER];                 // [g][tap][j][c]
__device__ __half xg_f16[(size_t)Bc * G * HW * CPER];         // [b][g][hw][c]

__device__ __forceinline__ uint32_t smem_u32(const void* p) {
    uint32_t a;
    asm("{ .reg .u64 t; cvta.to.shared.u64 t, %1; cvt.u32.u64 %0, t; }"
        : "=r"(a) : "l"(p));
    return a;
}

#define LDMX4(r0, r1, r2, r3, a) \
    asm volatile("ldmatrix.sync.aligned.m8n8.x4.shared.b16 {%0,%1,%2,%3}, [%4];" \
                 : "=r"(r0), "=r"(r1), "=r"(r2), "=r"(r3) : "r"(a))

#define MMA16816(d, a0, a1, a2, a3, b0, b1) \
    asm volatile("mma.sync.aligned.m16n8k16.row.col.f32.f16.f16.f32 " \
                 "{%0,%1,%2,%3}, {%4,%5,%6,%7}, {%8,%9}, {%0,%1,%2,%3};" \
                 : "+f"((d)[0]), "+f"((d)[1]), "+f"((d)[2]), "+f"((d)[3]) \
                 : "r"(a0), "r"(a1), "r"(a2), "r"(a3), "r"(b0), "r"(b1))

// ---- Prep 1: weights fp32 [g][j][c][tap] -> fp16 [g][tap][j][c]
__global__ void __launch_bounds__(256)
prep_weights_kernel(const float* __restrict__ wgt)
{
    int idx = blockIdx.x * 256 + threadIdx.x;
    if (idx >= G * 9 * Jc * CPER) return;
    int c   = idx & 31;
    int j   = (idx >> 5) & 63;
    int tap = (idx >> 11) % 9;
    int g   = idx / (9 * Jc * CPER);
    wgt_f16[idx] = __float2half(wgt[((size_t)(g * Jc + j) * CPER + c) * 9 + tap]);
}

// ---- Prep 2: x fp32 [b][256][h][w] -> gathered fp16 channels-last [b][g][hw][32c]
#define PREP_CHUNK 256
__global__ void __launch_bounds__(256)
prep_x_kernel(const float* __restrict__ x, const int* __restrict__ arr)
{
    __shared__ __half tile[PREP_CHUNK * 40];   // stride 40 halves (80 B, 16B-aligned)
    __shared__ int ch_s[CPER];

    const int tid = threadIdx.x;
    const int g   = blockIdx.x;
    const int b   = blockIdx.y;

    if (tid < CPER) ch_s[tid] = arr[g * CPER + tid];
    __syncthreads();

    const float* xb = x + (size_t)b * CIN * HW;
    uint4* dst = (uint4*)(xg_f16 + ((size_t)(b * G + g)) * HW * CPER);

    for (int hw0 = 0; hw0 < HW; hw0 += PREP_CHUNK) {
        int lim = HW - hw0;
        if (lim > PREP_CHUNK) lim = PREP_CHUNK;
        // load: coalesced per channel
        if (tid < lim) {
#pragma unroll 8
            for (int c = 0; c < CPER; ++c) {
                float v = xb[(size_t)ch_s[c] * HW + hw0 + tid];
                tile[tid * 40 + c] = __float2half(v);
            }
        }
        __syncthreads();
        // store: coalesced uint4 (each spatial pos = 4 uint4)
        for (int idx = tid; idx < lim * 4; idx += 256) {
            int s = idx >> 2, p = idx & 3;
            uint4 v = *(const uint4*)(tile + s * 40 + p * 8);
            dst[(size_t)(hw0 + s) * 4 + p] = v;
        }
        __syncthreads();
    }
}

// ---- Main: implicit-GEMM HMMA
__global__ void __launch_bounds__(NTHREADS, 2)
grouped_conv_hmma_kernel(const float* __restrict__ bias,
                         float*       __restrict__ out)
{
    extern __shared__ char dsm[];
    __shared__ float bias_s[Jc];

    const int tid  = threadIdx.x;
    const int wid  = tid >> 5;
    const int lane = tid & 31;

    const int g  = blockIdx.x;
    const int r0 = blockIdx.y * TILE_OR;
    const int b  = blockIdx.z;

    uint32_t raw  = smem_u32(dsm);
    uint32_t base = (raw + 1023u) & ~1023u;
    char* sm = dsm + (base - raw);
    const uint32_t smA = base + SM_A;
    const uint32_t smB = base + SM_B;

    if (tid < Jc) bias_s[tid] = bias[g * Jc + tid];

    // ---- Stage A: copy gathered fp16 rows (4 uint4 per spatial pos), halo zero
    {
        const uint4* xsrc = (const uint4*)(xg_f16 + ((size_t)(b * G + g)) * HW * CPER);
        for (int idx = tid; idx < NREAL * 4; idx += NTHREADS) {
            int n = idx >> 2, q = idx & 3;
            int ir = n / NCOLS;
            int ic = n - ir * NCOLS;
            int xr = r0 - 1 + ir;
            int xc = ic - 1;
            uint4 v = make_uint4(0u, 0u, 0u, 0u);
            if ((unsigned)xr < (unsigned)Hc && (unsigned)xc < (unsigned)Wc)
                v = xsrc[(size_t)(xr * Wc + xc) * 4 + q];
            *(uint4*)(sm + SM_A + n * RSTR + q * 16) = v;
        }
    }

    // ---- Stage B: 9 taps x 64 j x 64 B, coalesced uint4
    {
        const uint4* wsrc = (const uint4*)(wgt_f16 + (size_t)g * 9 * Jc * CPER);
        for (int idx = tid; idx < 9 * Jc * 4; idx += NTHREADS) {
            int q   = idx & 3;
            int j   = (idx >> 2) & 63;
            int tap = idx >> 8;
            uint4 v = wsrc[(size_t)(tap * Jc + j) * 4 + q];
            *(uint4*)(sm + SM_B + tap * BT_STR + j * RSTR + q * 16) = v;
        }
    }
    __syncthreads();

    // ---- MMA mainloop: warp w -> M rows [w*32, w*32+32), N=64
    const int m0 = wid * 32;
    float d[2][8][4];
#pragma unroll
    for (int mt = 0; mt < 2; ++mt)
#pragma unroll
        for (int nt = 0; nt < 8; ++nt)
#pragma unroll
            for (int k = 0; k < 4; ++k) d[mt][nt][k] = 0.0f;

    const int arow  = (lane & 7) + ((lane >> 3) & 1) * 8;
    const int akoff = (lane >> 4) * 16;
    const int brow  = (lane & 7) + (lane >> 4) * 8;
    const int bkoff = ((lane >> 3) & 1) * 16;

    const uint32_t aBase = smA + (m0 + arow) * RSTR + akoff;
    const uint32_t bBase = smB + brow * RSTR + bkoff;

#pragma unroll
    for (int ky = 0; ky < 3; ++ky) {
#pragma unroll
        for (int kx = 0; kx < 3; ++kx) {
            const int dlt = ky * NCOLS + kx;
            const uint32_t btap = bBase + (ky * 3 + kx) * BT_STR;
#pragma unroll
            for (int ks = 0; ks < 2; ++ks) {
                uint32_t af[2][4];
#pragma unroll
                for (int mt = 0; mt < 2; ++mt)
                    LDMX4(af[mt][0], af[mt][1], af[mt][2], af[mt][3],
                          aBase + (mt * 16 + dlt) * RSTR + ks * 32);
                uint32_t bf[8][2];
#pragma unroll
                for (int np = 0; np < 4; ++np)
                    LDMX4(bf[2 * np][0], bf[2 * np][1], bf[2 * np + 1][0], bf[2 * np + 1][1],
                          btap + np * 16 * RSTR + ks * 32);
#pragma unroll
                for (int mt = 0; mt < 2; ++mt)
#pragma unroll
                    for (int nt = 0; nt < 8; ++nt)
                        MMA16816(d[mt][nt], af[mt][0], af[mt][1], af[mt][2], af[mt][3],
                                 bf[nt][0], bf[nt][1]);
            }
        }
    }

    // ---- Epilogue: transpose through smem, coalesced stores
    __syncthreads();
    float* smO = (float*)sm;               // [64 j][OSTR]
#pragma unroll
    for (int mt = 0; mt < 2; ++mt) {
        int row = m0 + mt * 16 + (lane >> 2);
#pragma unroll
        for (int nt = 0; nt < 8; ++nt) {
            int j = nt * 8 + (lane & 3) * 2;
            smO[j * OSTR + row]           = d[mt][nt][0];
            smO[(j + 1) * OSTR + row]     = d[mt][nt][1];
            smO[j * OSTR + row + 8]       = d[mt][nt][2];
            smO[(j + 1) * OSTR + row + 8] = d[mt][nt][3];
        }
    }
    __syncthreads();

    {
        float* obase = out + ((size_t)b * (G * Jc) + g * Jc) * HW + (size_t)r0 * Wc;
        for (int idx = tid; idx < Jc * TILE_OR * Wc; idx += NTHREADS) {
            int j    = idx / (TILE_OR * Wc);
            int r    = idx - j * (TILE_OR * Wc);
            int orow = r / Wc;
            int oc   = r - orow * Wc;
            obase[(size_t)j * HW + orow * Wc + oc] =
                smO[j * OSTR + orow * NCOLS + oc] + bias_s[j];
        }
    }
}

extern "C" void kernel_launch(void* const* d_in, const int* in_sizes, int n_in,
                              void* d_out, int out_size)
{
    const float* x    = (const float*)d_in[0];
    const float* wgt  = (const float*)d_in[1];
    const float* bias = (const float*)d_in[2];
    const int*   arr  = (const int*)d_in[3];
    float* out = (float*)d_out;

    prep_weights_kernel<<<(G * 9 * Jc * CPER + 255) / 256, 256>>>(wgt);
    prep_x_kernel<<<dim3(G, Bc), 256>>>(x, arr);

    cudaFuncSetAttribute(grouped_conv_hmma_kernel,
                         cudaFuncAttributeMaxDynamicSharedMemorySize, SMEM_BYTES);

    dim3 grid(G, Hc / TILE_OR, Bc);   // (8, 14, 16) = 1792 blocks
    grouped_conv_hmma_kernel<<<grid, NTHREADS, SMEM_BYTES>>>(bias, out);
}

// round 8
// speedup vs baseline: 2.2601x; 2.2601x over previous
#include <cuda_runtime.h>
#include <cuda_fp16.h>
#include <cstdint>

// Problem constants
#define Bc   16
#define G    8
#define CPER 32
#define CIN  256
#define Jc   64
#define Hc   56
#define Wc   56
#define HW   (Hc * Wc)          // 3136

// Tiling
#define TILE_OR 4
#define NCOLS   58
#define NREAL   ((TILE_OR + 2) * NCOLS)   // 348
#define NPADR   384
#define NSPAT   (TILE_OR * NCOLS)         // 232
#define NTHREADS 256

// smem rows: 80 B (64 B data + 16 B pad) -> conflict-free ldmatrix, cheap addressing
#define RSTR    80
#define SM_A    0
#define SM_B    (NPADR * RSTR)            // 30720
#define BT_STR  (Jc * RSTR)               // 5120 per tap
#define SMEM_USED (SM_B + 9 * BT_STR)     // 76800
#define SMEM_BYTES (SMEM_USED + 1024)

#define OSTR 260                          // epilogue scratch stride (floats)

// Prepped operands
__device__ __half wgt_f16[G * 9 * Jc * CPER];                 // [g][tap][j][c]
__device__ __half xg_f16[(size_t)Bc * G * HW * CPER];         // [b][g][hw][c]

__device__ __forceinline__ uint32_t smem_u32(const void* p) {
    uint32_t a;
    asm("{ .reg .u64 t; cvta.to.shared.u64 t, %1; cvt.u32.u64 %0, t; }"
        : "=r"(a) : "l"(p));
    return a;
}

#define LDMX4(r0, r1, r2, r3, a) \
    asm volatile("ldmatrix.sync.aligned.m8n8.x4.shared.b16 {%0,%1,%2,%3}, [%4];" \
                 : "=r"(r0), "=r"(r1), "=r"(r2), "=r"(r3) : "r"(a))

#define MMA16816(d, a0, a1, a2, a3, b0, b1) \
    asm volatile("mma.sync.aligned.m16n8k16.row.col.f32.f16.f16.f32 " \
                 "{%0,%1,%2,%3}, {%4,%5,%6,%7}, {%8,%9}, {%0,%1,%2,%3};" \
                 : "+f"((d)[0]), "+f"((d)[1]), "+f"((d)[2]), "+f"((d)[3]) \
                 : "r"(a0), "r"(a1), "r"(a2), "r"(a3), "r"(b0), "r"(b1))

// ---- Prep 1: weights fp32 [g][j][c][tap] -> fp16 [g][tap][j][c]
__global__ void __launch_bounds__(256)
prep_weights_kernel(const float* __restrict__ wgt)
{
    int idx = blockIdx.x * 256 + threadIdx.x;
    if (idx >= G * 9 * Jc * CPER) return;
    int c   = idx & 31;
    int j   = (idx >> 5) & 63;
    int tap = (idx >> 11) % 9;
    int g   = idx / (9 * Jc * CPER);
    wgt_f16[idx] = __float2half(wgt[((size_t)(g * Jc + j) * CPER + c) * 9 + tap]);
}

// ---- Prep 2: x fp32 [b][256][h][w] -> gathered fp16 channels-last [b][g][hw][32c]
// One block per (g, band of 8 rows = 448 positions, b): 896 blocks.
#define BAND 448
__global__ void __launch_bounds__(256)
prep_x_kernel(const float* __restrict__ x, const int* __restrict__ arr)
{
    __shared__ __half tile[BAND * 40];   // stride 40 halves (80 B), 35840 B
    __shared__ int ch_s[CPER];

    const int tid  = threadIdx.x;
    const int g    = blockIdx.x;
    const int hw0  = blockIdx.y * BAND;
    const int b    = blockIdx.z;

    if (tid < CPER) ch_s[tid] = arr[g * CPER + tid];
    __syncthreads();

    const float* xb = x + (size_t)b * CIN * HW + hw0;

    // load: for each channel, 448 consecutive fp32 (coalesced); transpose into smem
#pragma unroll 2
    for (int s = tid; s < BAND; s += 256) {
#pragma unroll 8
        for (int c = 0; c < CPER; ++c) {
            tile[s * 40 + c] = __float2half(xb[(size_t)ch_s[c] * HW + s]);
        }
    }
    __syncthreads();

    // store: coalesced uint4 (each position = 4 uint4)
    uint4* dst = (uint4*)(xg_f16 + ((size_t)(b * G + g) * HW + hw0) * CPER);
    for (int idx = tid; idx < BAND * 4; idx += 256) {
        int s = idx >> 2, p = idx & 3;
        dst[(size_t)s * 4 + p] = *(const uint4*)(tile + s * 40 + p * 8);
    }
}

// ---- Main: implicit-GEMM HMMA
__global__ void __launch_bounds__(NTHREADS, 2)
grouped_conv_hmma_kernel(const float* __restrict__ bias,
                         float*       __restrict__ out)
{
    extern __shared__ char dsm[];
    __shared__ float bias_s[Jc];

    const int tid  = threadIdx.x;
    const int wid  = tid >> 5;
    const int lane = tid & 31;

    const int g  = blockIdx.x;
    const int r0 = blockIdx.y * TILE_OR;
    const int b  = blockIdx.z;

    uint32_t raw  = smem_u32(dsm);
    uint32_t base = (raw + 1023u) & ~1023u;
    char* sm = dsm + (base - raw);
    const uint32_t smA = base + SM_A;
    const uint32_t smB = base + SM_B;

    if (tid < Jc) bias_s[tid] = bias[g * Jc + tid];

    // ---- Stage A: copy gathered fp16 rows (4 uint4 per spatial pos), halo zero
    {
        const uint4* xsrc = (const uint4*)(xg_f16 + ((size_t)(b * G + g)) * HW * CPER);
        for (int idx = tid; idx < NREAL * 4; idx += NTHREADS) {
            int n = idx >> 2, q = idx & 3;
            int ir = n / NCOLS;
            int ic = n - ir * NCOLS;
            int xr = r0 - 1 + ir;
            int xc = ic - 1;
            uint4 v = make_uint4(0u, 0u, 0u, 0u);
            if ((unsigned)xr < (unsigned)Hc && (unsigned)xc < (unsigned)Wc)
                v = xsrc[(size_t)(xr * Wc + xc) * 4 + q];
            *(uint4*)(sm + SM_A + n * RSTR + q * 16) = v;
        }
    }

    // ---- Stage B: 9 taps x 64 j x 64 B, coalesced uint4
    {
        const uint4* wsrc = (const uint4*)(wgt_f16 + (size_t)g * 9 * Jc * CPER);
        for (int idx = tid; idx < 9 * Jc * 4; idx += NTHREADS) {
            int q   = idx & 3;
            int j   = (idx >> 2) & 63;
            int tap = idx >> 8;
            uint4 v = wsrc[(size_t)(tap * Jc + j) * 4 + q];
            *(uint4*)(sm + SM_B + tap * BT_STR + j * RSTR + q * 16) = v;
        }
    }
    __syncthreads();

    // ---- MMA mainloop: warp w -> M rows [w*32, w*32+32), N=64
    const int m0 = wid * 32;
    float d[2][8][4];
#pragma unroll
    for (int mt = 0; mt < 2; ++mt)
#pragma unroll
        for (int nt = 0; nt < 8; ++nt)
#pragma unroll
            for (int k = 0; k < 4; ++k) d[mt][nt][k] = 0.0f;

    const int arow  = (lane & 7) + ((lane >> 3) & 1) * 8;
    const int akoff = (lane >> 4) * 16;
    const int brow  = (lane & 7) + (lane >> 4) * 8;
    const int bkoff = ((lane >> 3) & 1) * 16;

    const uint32_t aBase = smA + (m0 + arow) * RSTR + akoff;
    const uint32_t bBase = smB + brow * RSTR + bkoff;

#pragma unroll
    for (int ky = 0; ky < 3; ++ky) {
#pragma unroll
        for (int kx = 0; kx < 3; ++kx) {
            const int dlt = ky * NCOLS + kx;
            const uint32_t btap = bBase + (ky * 3 + kx) * BT_STR;
#pragma unroll
            for (int ks = 0; ks < 2; ++ks) {
                uint32_t af[2][4];
#pragma unroll
                for (int mt = 0; mt < 2; ++mt)
                    LDMX4(af[mt][0], af[mt][1], af[mt][2], af[mt][3],
                          aBase + (mt * 16 + dlt) * RSTR + ks * 32);
                uint32_t bf[8][2];
#pragma unroll
                for (int np = 0; np < 4; ++np)
                    LDMX4(bf[2 * np][0], bf[2 * np][1], bf[2 * np + 1][0], bf[2 * np + 1][1],
                          btap + np * 16 * RSTR + ks * 32);
#pragma unroll
                for (int mt = 0; mt < 2; ++mt)
#pragma unroll
                    for (int nt = 0; nt < 8; ++nt)
                        MMA16816(d[mt][nt], af[mt][0], af[mt][1], af[mt][2], af[mt][3],
                                 bf[nt][0], bf[nt][1]);
            }
        }
    }

    // ---- Epilogue: transpose through smem, coalesced stores
    __syncthreads();
    float* smO = (float*)sm;               // [64 j][OSTR]
#pragma unroll
    for (int mt = 0; mt < 2; ++mt) {
        int row = m0 + mt * 16 + (lane >> 2);
#pragma unroll
        for (int nt = 0; nt < 8; ++nt) {
            int j = nt * 8 + (lane & 3) * 2;
            smO[j * OSTR + row]           = d[mt][nt][0];
            smO[(j + 1) * OSTR + row]     = d[mt][nt][1];
            smO[j * OSTR + row + 8]       = d[mt][nt][2];
            smO[(j + 1) * OSTR + row + 8] = d[mt][nt][3];
        }
    }
    __syncthreads();

    {
        float* obase = out + ((size_t)b * (G * Jc) + g * Jc) * HW + (size_t)r0 * Wc;
        for (int idx = tid; idx < Jc * TILE_OR * Wc; idx += NTHREADS) {
            int j    = idx / (TILE_OR * Wc);
            int r    = idx - j * (TILE_OR * Wc);
            int orow = r / Wc;
            int oc   = r - orow * Wc;
            obase[(size_t)j * HW + orow * Wc + oc] =
                smO[j * OSTR + orow * NCOLS + oc] + bias_s[j];
        }
    }
}

extern "C" void kernel_launch(void* const* d_in, const int* in_sizes, int n_in,
                              void* d_out, int out_size)
{
    const float* x    = (const float*)d_in[0];
    const float* wgt  = (const float*)d_in[1];
    const float* bias = (const float*)d_in[2];
    const int*   arr  = (const int*)d_in[3];
    float* out = (float*)d_out;

    prep_weights_kernel<<<(G * 9 * Jc * CPER + 255) / 256, 256>>>(wgt);
    prep_x_kernel<<<dim3(G, HW / BAND, Bc), 256>>>(x, arr);   // (8, 7, 16) = 896 blocks

    cudaFuncSetAttribute(grouped_conv_hmma_kernel,
                         cudaFuncAttributeMaxDynamicSharedMemorySize, SMEM_BYTES);

    dim3 grid(G, Hc / TILE_OR, Bc);   // (8, 14, 16) = 1792 blocks
    grouped_conv_hmma_kernel<<<grid, NTHREADS, SMEM_BYTES>>>(bias, out);
}

// round 9
// speedup vs baseline: 2.5708x; 1.1374x over previous
#include <cuda_runtime.h>
#include <cuda_fp16.h>
#include <cstdint>

// Problem constants
#define Bc   16
#define G    8
#define CPER 32
#define CIN  256
#define Jc   64
#define Hc   56
#define Wc   56
#define HW   (Hc * Wc)          // 3136

// Padded-x layout: 58 rows (1 halo top/bottom), 60 cols (col ic = input col ic-1)
#define PROWS 58
#define PCOLS 60

// Tiling
#define TILE_OR 4
#define NREAL   ((TILE_OR + 2) * PCOLS)   // 360 staged spatial rows
#define NPADR   384
#define NSPAT   (TILE_OR * PCOLS)         // 240
#define NTHREADS 256

// smem rows: 80 B (64 B data + 16 B pad)
#define RSTR    80
#define SM_A    0
#define SM_B    (NPADR * RSTR)            // 30720
#define BT_STR  (Jc * RSTR)               // 5120 per tap
#define SMEM_USED (SM_B + 9 * BT_STR)     // 76800
#define SMEM_BYTES (SMEM_USED + 1024)

#define OSTR 260                          // epilogue scratch stride (floats)

// Prepped operands
__device__ __half wgt_f16[G * 9 * Jc * CPER];                       // [g][tap][j][c]
__device__ __half xg_f16[(size_t)Bc * G * PROWS * PCOLS * CPER];    // padded

__device__ __forceinline__ uint32_t smem_u32(const void* p) {
    uint32_t a;
    asm("{ .reg .u64 t; cvta.to.shared.u64 t, %1; cvt.u32.u64 %0, t; }"
        : "=r"(a) : "l"(p));
    return a;
}

#define LDMX4(r0, r1, r2, r3, a) \
    asm volatile("ldmatrix.sync.aligned.m8n8.x4.shared.b16 {%0,%1,%2,%3}, [%4];" \
                 : "=r"(r0), "=r"(r1), "=r"(r2), "=r"(r3) : "r"(a))

#define MMA16816(d, a0, a1, a2, a3, b0, b1) \
    asm volatile("mma.sync.aligned.m16n8k16.row.col.f32.f16.f16.f32 " \
                 "{%0,%1,%2,%3}, {%4,%5,%6,%7}, {%8,%9}, {%0,%1,%2,%3};" \
                 : "+f"((d)[0]), "+f"((d)[1]), "+f"((d)[2]), "+f"((d)[3]) \
                 : "r"(a0), "r"(a1), "r"(a2), "r"(a3), "r"(b0), "r"(b1))

// ---- Prep 1: weights fp32 [g][j][c][tap] -> fp16 [g][tap][j][c]
__global__ void __launch_bounds__(256)
prep_weights_kernel(const float* __restrict__ wgt)
{
    int idx = blockIdx.x * 256 + threadIdx.x;
    if (idx >= G * 9 * Jc * CPER) return;
    int c   = idx & 31;
    int j   = (idx >> 5) & 63;
    int tap = (idx >> 11) % 9;
    int g   = idx / (9 * Jc * CPER);
    wgt_f16[idx] = __float2half(wgt[((size_t)(g * Jc + j) * CPER + c) * 9 + tap]);
}

// ---- Prep 2: x -> gathered fp16, zero-padded [b][g][58][60][32c]
// Block = (g, band of 4 padded rows, b); 15 bands cover rows 0..57.
__global__ void __launch_bounds__(256)
prep_x_kernel(const float* __restrict__ x, const int* __restrict__ arr)
{
    __shared__ __half tile[4 * PCOLS * 40];   // 4 rows x 60 cols, stride 40 halves
    __shared__ int ch_s[CPER];

    const int tid  = threadIdx.x;
    const int g    = blockIdx.x;
    const int pr0  = blockIdx.y * 4;
    const int b    = blockIdx.z;

    if (tid < CPER) ch_s[tid] = arr[g * CPER + tid];
    // zero tile (covers halo cols/rows)
    {
        uint4* t4 = (uint4*)tile;
        for (int i = tid; i < 4 * PCOLS * 40 / 8; i += 256)
            t4[i] = make_uint4(0u, 0u, 0u, 0u);
    }
    __syncthreads();

    const float* xb = x + (size_t)b * CIN * HW;
    // fill: idx -> c (slowest), row, col (fastest, coalesced)
    for (int idx = tid; idx < CPER * 4 * Wc; idx += 256) {
        int col = idx % Wc;
        int t   = idx / Wc;
        int row = t & 3;
        int c   = t >> 2;
        int pr  = pr0 + row;
        int xr  = pr - 1;
        if (pr < PROWS && (unsigned)xr < (unsigned)Hc) {
            tile[(row * PCOLS + col + 1) * 40 + c] =
                __float2half(xb[(size_t)ch_s[c] * HW + xr * Wc + col]);
        }
    }
    __syncthreads();

    // store coalesced uint4: 4 rows x 60 cols x 4 uint4
    uint4* dst = (uint4*)(xg_f16 + ((size_t)(b * G + g) * PROWS + pr0) * PCOLS * CPER);
    int nrows = (pr0 + 4 <= PROWS) ? 4 : (PROWS - pr0);
    for (int idx = tid; idx < nrows * PCOLS * 4; idx += 256) {
        int s = idx >> 2, p = idx & 3;
        dst[(size_t)s * 4 + p] = *(const uint4*)(tile + s * 40 + p * 8);
    }
}

// ---- Main: implicit-GEMM HMMA
__global__ void __launch_bounds__(NTHREADS, 2)
grouped_conv_hmma_kernel(const float* __restrict__ bias,
                         float*       __restrict__ out)
{
    extern __shared__ char dsm[];
    __shared__ float bias_s[Jc];

    const int tid  = threadIdx.x;
    const int wid  = tid >> 5;
    const int lane = tid & 31;

    const int g  = blockIdx.x;
    const int r0 = blockIdx.y * TILE_OR;
    const int b  = blockIdx.z;

    uint32_t raw  = smem_u32(dsm);
    uint32_t base = (raw + 1023u) & ~1023u;
    char* sm = dsm + (base - raw);
    const uint32_t smA = base + SM_A;
    const uint32_t smB = base + SM_B;

    if (tid < Jc) bias_s[tid] = bias[g * Jc + tid];

    // ---- Stage A: pure contiguous copy (halo pre-baked), 1440 uint4
    {
        const uint4* xsrc = (const uint4*)(xg_f16
            + ((size_t)(b * G + g) * PROWS) * PCOLS * CPER) + (size_t)r0 * PCOLS * 4;
        for (int idx = tid; idx < NREAL * 4; idx += NTHREADS) {
            int n = idx >> 2, q = idx & 3;
            *(uint4*)(sm + SM_A + n * RSTR + q * 16) = xsrc[idx];
        }
    }

    // ---- Stage B: 9 taps x 64 j x 64 B, coalesced uint4
    {
        const uint4* wsrc = (const uint4*)(wgt_f16 + (size_t)g * 9 * Jc * CPER);
        for (int idx = tid; idx < 9 * Jc * 4; idx += NTHREADS) {
            int q   = idx & 3;
            int j   = (idx >> 2) & 63;
            int tap = idx >> 8;
            *(uint4*)(sm + SM_B + tap * BT_STR + j * RSTR + q * 16) =
                wsrc[(size_t)(tap * Jc + j) * 4 + q];
        }
    }
    __syncthreads();

    // ---- MMA mainloop: warp w -> M rows [w*32, w*32+32), N=64
    const int m0 = wid * 32;
    float d[2][8][4];
#pragma unroll
    for (int mt = 0; mt < 2; ++mt)
#pragma unroll
        for (int nt = 0; nt < 8; ++nt)
#pragma unroll
            for (int k = 0; k < 4; ++k) d[mt][nt][k] = 0.0f;

    const int arow  = (lane & 7) + ((lane >> 3) & 1) * 8;
    const int akoff = (lane >> 4) * 16;
    const int brow  = (lane & 7) + (lane >> 4) * 8;
    const int bkoff = ((lane >> 3) & 1) * 16;

    const uint32_t aBase = smA + (m0 + arow) * RSTR + akoff;
    const uint32_t bBase = smB + brow * RSTR + bkoff;

#pragma unroll
    for (int ky = 0; ky < 3; ++ky) {
#pragma unroll
        for (int kx = 0; kx < 3; ++kx) {
            const int dlt = ky * PCOLS + kx;
            const uint32_t btap = bBase + (ky * 3 + kx) * BT_STR;
#pragma unroll
            for (int ks = 0; ks < 2; ++ks) {
                uint32_t af[2][4];
#pragma unroll
                for (int mt = 0; mt < 2; ++mt)
                    LDMX4(af[mt][0], af[mt][1], af[mt][2], af[mt][3],
                          aBase + (mt * 16 + dlt) * RSTR + ks * 32);
                uint32_t bf[8][2];
#pragma unroll
                for (int np = 0; np < 4; ++np)
                    LDMX4(bf[2 * np][0], bf[2 * np][1], bf[2 * np + 1][0], bf[2 * np + 1][1],
                          btap + np * 16 * RSTR + ks * 32);
#pragma unroll
                for (int mt = 0; mt < 2; ++mt)
#pragma unroll
                    for (int nt = 0; nt < 8; ++nt)
                        MMA16816(d[mt][nt], af[mt][0], af[mt][1], af[mt][2], af[mt][3],
                                 bf[nt][0], bf[nt][1]);
            }
        }
    }

    // ---- Epilogue: transpose through smem, vectorized coalesced stores
    __syncthreads();
    float* smO = (float*)sm;               // [64 j][OSTR floats]
#pragma unroll
    for (int mt = 0; mt < 2; ++mt) {
        int row = m0 + mt * 16 + (lane >> 2);
#pragma unroll
        for (int nt = 0; nt < 8; ++nt) {
            int j = nt * 8 + (lane & 3) * 2;
            smO[j * OSTR + row]           = d[mt][nt][0];
            smO[(j + 1) * OSTR + row]     = d[mt][nt][1];
            smO[j * OSTR + row + 8]       = d[mt][nt][2];
            smO[(j + 1) * OSTR + row + 8] = d[mt][nt][3];
        }
    }
    __syncthreads();

    {
        float* obase = out + ((size_t)b * (G * Jc) + g * Jc) * HW + (size_t)r0 * Wc;
        // 64 j x 4 rows x 14 uint4
        for (int idx = tid; idx < Jc * TILE_OR * 14; idx += NTHREADS) {
            int j    = idx / (TILE_OR * 14);
            int rem  = idx - j * (TILE_OR * 14);
            int orow = rem / 14;
            int q    = rem - orow * 14;
            float4 v = *(const float4*)(smO + j * OSTR + orow * PCOLS + q * 4);
            float bv = bias_s[j];
            v.x += bv; v.y += bv; v.z += bv; v.w += bv;
            *(float4*)(obase + (size_t)j * HW + orow * Wc + q * 4) = v;
        }
    }
}

extern "C" void kernel_launch(void* const* d_in, const int* in_sizes, int n_in,
                              void* d_out, int out_size)
{
    const float* x    = (const float*)d_in[0];
    const float* wgt  = (const float*)d_in[1];
    const float* bias = (const float*)d_in[2];
    const int*   arr  = (const int*)d_in[3];
    float* out = (float*)d_out;

    prep_weights_kernel<<<(G * 9 * Jc * CPER + 255) / 256, 256>>>(wgt);
    prep_x_kernel<<<dim3(G, 15, Bc), 256>>>(x, arr);   // 1920 blocks

    cudaFuncSetAttribute(grouped_conv_hmma_kernel,
                         cudaFuncAttributeMaxDynamicSharedMemorySize, SMEM_BYTES);

    dim3 grid(G, Hc / TILE_OR, Bc);   // (8, 14, 16) = 1792 blocks
    grouped_conv_hmma_kernel<<<grid, NTHREADS, SMEM_BYTES>>>(bias, out);
}